// round 16
// baseline (speedup 1.0000x reference)
#include <cuda_runtime.h>
#include <cstdint>

// ---------------- problem constants ----------------
#define NB   4
#define C64  64
#define CR   32
#define HLq  96
#define WLq  96
#define HSk  48
#define WSk  48
#define Pq   (HLq*WLq)     // 9216 queries
#define Lk   (HSk*WSk)     // 2304 keys

// ---------------- device scratch (static, allocation-free) ----------------
__device__ float g_mb     [(size_t)NB*CR*Pq];    // match_base [N,32,96,96]
__device__ float g_ref    [(size_t)NB*CR*Lk];    // ref        [N,32,48,48]
__device__ float g_base   [(size_t)NB*C64*Lk];   // base       [N,64,48,48]
__device__ float g_baseT  [(size_t)NB*Lk*C64];   // base^T     [N,2304,64]
__device__ float g_S      [(size_t)NB*Lk];       // per-pixel sum of ref^2
__device__ float g_invnorm[(size_t)NB*Lk];       // 1/(||w_patch||+eps)
__device__ float g_probs  [(size_t)NB*Pq*Lk];    // ping buffer
__device__ float g_G      [(size_t)NB*Pq*Lk];    // pong buffer

// ---------------- 1x1 conv + PReLU ----------------
template<int CO, int HW>
__device__ __forceinline__ void conv_body(const float* __restrict__ in,
                                          const float* __restrict__ w,
                                          const float* __restrict__ b,
                                          const float* __restrict__ a,
                                          float* __restrict__ out) {
    __shared__ float ws[CO*64];
    __shared__ float bs[CO];
    int tid = threadIdx.x;
    for (int i = tid; i < CO*64; i += 256) ws[i] = w[i];
    for (int i = tid; i < CO;    i += 256) bs[i] = b[i];
    __syncthreads();
    float alpha = __ldg(a);
    int n = blockIdx.y;
    int p = (blockIdx.x << 8) + tid;
    const float* inp = in + (size_t)n*64*HW + p;
    float acc[CO];
#pragma unroll
    for (int co = 0; co < CO; co++) acc[co] = bs[co];
    for (int ci = 0; ci < 64; ci++) {
        float x = inp[(size_t)ci*HW];
#pragma unroll
        for (int co = 0; co < CO; co++) acc[co] = fmaf(ws[co*64+ci], x, acc[co]);
    }
    float* op = out + (size_t)n*CO*HW + p;
#pragma unroll
    for (int co = 0; co < CO; co++) {
        float v = acc[co];
        op[(size_t)co*HW] = v >= 0.f ? v : alpha*v;
    }
}

__global__ __launch_bounds__(256) void k_conv_mb(const float* __restrict__ in,
    const float* __restrict__ w, const float* __restrict__ b, const float* __restrict__ a) {
    conv_body<CR, Pq>(in, w, b, a, g_mb);
}
__global__ __launch_bounds__(256) void k_conv_ref(const float* __restrict__ in,
    const float* __restrict__ w, const float* __restrict__ b, const float* __restrict__ a) {
    conv_body<CR, Lk>(in, w, b, a, g_ref);
}
__global__ __launch_bounds__(256) void k_conv_base(const float* __restrict__ in,
    const float* __restrict__ w, const float* __restrict__ b, const float* __restrict__ a) {
    conv_body<C64, Lk>(in, w, b, a, g_base);
}

// ---------------- transpose base -> [N, L, 64] ----------------
__global__ __launch_bounds__(256) void k_baseT() {
    int idx = (blockIdx.x << 8) + threadIdx.x;     // over NB*Lk*64 (exact)
    int c = idx & 63;
    int t = idx >> 6;
    int l = t % Lk;
    int n = t / Lk;
    g_baseT[idx] = g_base[((size_t)n*C64 + c)*Lk + l];
}

// ---------------- S[n][u] = sum_c ref[n][c][u]^2 ----------------
__global__ __launch_bounds__(256) void k_S() {
    int idx = (blockIdx.x << 8) + threadIdx.x;     // over NB*Lk (exact: 36 blocks)
    int u = idx % Lk, n = idx / Lk;
    const float* r = g_ref + (size_t)n*CR*Lk + u;
    float s = 0.f;
#pragma unroll
    for (int c = 0; c < CR; c++) { float v = r[(size_t)c*Lk]; s = fmaf(v, v, s); }
    g_S[idx] = s;
}

// ---------------- invnorm[n][l] = 1/(sqrt(sum_{3x3 in-bounds} S) + eps) ----------------
__global__ __launch_bounds__(256) void k_invnorm() {
    int idx = (blockIdx.x << 8) + threadIdx.x;     // over NB*Lk
    int l = idx % Lk, n = idx / Lk;
    int hb = l / WSk, wb = l % WSk;
    const float* S = g_S + (size_t)n*Lk;
    float s = 0.f;
#pragma unroll
    for (int dy = -1; dy <= 1; dy++) {
        if ((unsigned)(hb + dy) >= HSk) continue;
#pragma unroll
        for (int dx = -1; dx <= 1; dx++) {
            if ((unsigned)(wb + dx) >= WSk) continue;
            s += S[l + dy*WSk + dx];
        }
    }
    g_invnorm[idx] = 1.f / (sqrtf(s) + 1e-4f);
}

// ---------------- R GEMM: g_G = mb^T @ ref  (M=9216, N=2304, K=32, per sample) ----------------
__global__ __launch_bounds__(256) void k_gemm_R() {
    __shared__ float As[32][128];
    __shared__ float Bs[32][128];
    const int n = blockIdx.z;
    const int bm = blockIdx.y << 7;
    const int bn = blockIdx.x << 7;
    const float* A = g_mb  + (size_t)n*CR*Pq;   // [c][p]
    const float* B = g_ref + (size_t)n*CR*Lk;   // [c][l]
    float* Cm = g_G + (size_t)n*Pq*Lk;
    const int tid = threadIdx.x;
#pragma unroll
    for (int i = 0; i < 16; i++) {
        int idx = tid + (i << 8);               // 0..4095
        int c = idx >> 7, x = idx & 127;
        As[c][x] = A[(size_t)c*Pq + bm + x];
        Bs[c][x] = B[(size_t)c*Lk + bn + x];
    }
    __syncthreads();
    const int ty = tid >> 4, tx = tid & 15;
    float acc[8][8];
#pragma unroll
    for (int i = 0; i < 8; i++)
#pragma unroll
        for (int j = 0; j < 8; j++) acc[i][j] = 0.f;
#pragma unroll
    for (int k = 0; k < 32; k++) {
        float ar[8], br[8];
        *reinterpret_cast<float4*>(&ar[0]) = *reinterpret_cast<float4*>(&As[k][ty<<3]);
        *reinterpret_cast<float4*>(&ar[4]) = *reinterpret_cast<float4*>(&As[k][(ty<<3)+4]);
        *reinterpret_cast<float4*>(&br[0]) = *reinterpret_cast<float4*>(&Bs[k][tx<<3]);
        *reinterpret_cast<float4*>(&br[4]) = *reinterpret_cast<float4*>(&Bs[k][(tx<<3)+4]);
#pragma unroll
        for (int i = 0; i < 8; i++)
#pragma unroll
            for (int j = 0; j < 8; j++) acc[i][j] = fmaf(ar[i], br[j], acc[i][j]);
    }
#pragma unroll
    for (int i = 0; i < 8; i++) {
        size_t off = (size_t)(bm + (ty<<3) + i)*Lk + bn + (tx<<3);
        *reinterpret_cast<float4*>(Cm + off)     = *reinterpret_cast<float4*>(&acc[i][0]);
        *reinterpret_cast<float4*>(Cm + off + 4) = *reinterpret_cast<float4*>(&acc[i][4]);
    }
}

// ---------------- w-pass diagonal stencil: g_G -> g_probs (used twice) ----------------
__global__ __launch_bounds__(256) void k_stencil_w2() {
    int l = (blockIdx.x << 8) + threadIdx.x;
    int p = blockIdx.y, n = blockIdx.z;
    const float* r = g_G + ((size_t)n*Pq + p) * (size_t)Lk;
    int wq = p % WLq;
    int wb = l % WSk;
    float s = r[l];
    if (wq > 0      && wb > 0)      s += r[(long)l - (Lk + 1)];
    if (wq < WLq-1  && wb < WSk-1)  s += r[(long)l + (Lk + 1)];
    g_probs[((size_t)n*Pq + p)*(size_t)Lk + l] = s;
}

// ---------------- fused h-pass stencil + scale(10*invnorm) + softmax ----------------
// reads T = g_probs rows {p-96, p, p+96}; writes probs row p to g_G
__global__ __launch_bounds__(288) void k_h_softmax() {
    int p = blockIdx.x, n = blockIdx.y;
    const float* T = g_probs + ((size_t)n*Pq + p) * (size_t)Lk;
    float* outp    = g_G     + ((size_t)n*Pq + p) * (size_t)Lk;
    const float* invn = g_invnorm + (size_t)n*Lk;
    int t = threadIdx.x;
    int hq = p / WLq;
    bool up_p = hq > 0, dn_p = hq < HLq-1;
    const float* Tu = T - (size_t)WLq*Lk - 48;   // row p-96, shifted -48
    const float* Td = T + (size_t)WLq*Lk + 48;   // row p+96, shifted +48
    float4 v[2];
    float m = -1e30f;
#pragma unroll
    for (int i = 0; i < 2; i++) {
        int f = i*288 + t;          // float4 index 0..575
        int l = f << 2;
        int hb = f / 12;            // = l/48 (float4 never straddles a 48-block)
        float4 s = *reinterpret_cast<const float4*>(T + l);
        if (up_p && hb > 0) {
            float4 u = *reinterpret_cast<const float4*>(Tu + l);
            s.x += u.x; s.y += u.y; s.z += u.z; s.w += u.w;
        }
        if (dn_p && hb < HSk-1) {
            float4 u = *reinterpret_cast<const float4*>(Td + l);
            s.x += u.x; s.y += u.y; s.z += u.z; s.w += u.w;
        }
        float4 iv = *reinterpret_cast<const float4*>(invn + l);
        s.x *= 10.f*iv.x; s.y *= 10.f*iv.y; s.z *= 10.f*iv.z; s.w *= 10.f*iv.w;
        v[i] = s;
        m = fmaxf(m, fmaxf(fmaxf(s.x, s.y), fmaxf(s.z, s.w)));
    }
    __shared__ float red[9];
    __shared__ float bval;
#pragma unroll
    for (int o = 16; o > 0; o >>= 1) m = fmaxf(m, __shfl_xor_sync(0xffffffffu, m, o));
    if ((t & 31) == 0) red[t >> 5] = m;
    __syncthreads();
    if (t == 0) {
        float x = red[0];
#pragma unroll
        for (int i = 1; i < 9; i++) x = fmaxf(x, red[i]);
        bval = x;
    }
    __syncthreads();
    float mm = bval;
    float s = 0.f;
#pragma unroll
    for (int i = 0; i < 2; i++) {
        v[i].x = expf(v[i].x - mm); v[i].y = expf(v[i].y - mm);
        v[i].z = expf(v[i].z - mm); v[i].w = expf(v[i].w - mm);
        s += v[i].x + v[i].y + v[i].z + v[i].w;
    }
#pragma unroll
    for (int o = 16; o > 0; o >>= 1) s += __shfl_xor_sync(0xffffffffu, s, o);
    if ((t & 31) == 0) red[t >> 5] = s;
    __syncthreads();
    if (t == 0) {
        float x = 0.f;
#pragma unroll
        for (int i = 0; i < 9; i++) x += red[i];
        bval = x;
    }
    __syncthreads();
    float inv = 1.f / bval;
#pragma unroll
    for (int i = 0; i < 2; i++) {
        int l = (i*288 + t) << 2;
        float4 o;
        o.x = v[i].x*inv; o.y = v[i].y*inv; o.z = v[i].z*inv; o.w = v[i].w*inv;
        *reinterpret_cast<float4*>(outp + l) = o;
    }
}

// ---------------- output GEMM with fused h-pass on A: ----------------
// A[p,k] = T2[p,k] + m*T2[p-96,k-48] + m*T2[p+96,k+48]  (T2 = g_probs)
// y = 0.25 * A @ baseT + input_l ; M=9216, N=64, K=2304; 128x64 tile, BK=16
__global__ __launch_bounds__(256) void k_sgemm_out(const float* __restrict__ inl,
                                                   float* __restrict__ out) {
    __shared__ float As[16][128];
    __shared__ float Bs[16][64];
    const int n = blockIdx.y;
    const float* A = g_probs + (size_t)n*Pq*Lk;
    const float* B = g_baseT + (size_t)n*Lk*C64;
    const int bm = blockIdx.x << 7;
    const int tid  = threadIdx.x;
    const int arow = tid & 127, acol = (tid >> 7) << 3;   // 0 or 8
    const int brow = tid >> 4,  bcol = (tid & 15) << 2;
    const int ty = tid >> 4, tx = tid & 15;
    const int p = bm + arow;
    const int hq = p / WLq;
    const bool up_p = hq > 0, dn_p = hq < HLq-1;
    const float* Ap  = A + (size_t)p*Lk;
    const float* Apu = Ap - (size_t)WLq*Lk - 48;
    const float* Apd = Ap + (size_t)WLq*Lk + 48;
    const float* Bptr = B + (size_t)brow*C64 + bcol;
    float acc[8][4];
#pragma unroll
    for (int i = 0; i < 8; i++)
#pragma unroll
        for (int j = 0; j < 4; j++) acc[i][j] = 0.f;
    for (int k0 = 0; k0 < Lk; k0 += 16) {
#pragma unroll
        for (int g = 0; g < 8; g += 4) {
            int k = k0 + acol + g;
            int hb = k / 48;                    // float4 never straddles (48%4==0)
            float4 a = *reinterpret_cast<const float4*>(Ap + k);
            if (up_p && hb > 0) {
                float4 u = *reinterpret_cast<const float4*>(Apu + k);
                a.x += u.x; a.y += u.y; a.z += u.z; a.w += u.w;
            }
            if (dn_p && hb < HSk-1) {
                float4 u = *reinterpret_cast<const float4*>(Apd + k);
                a.x += u.x; a.y += u.y; a.z += u.z; a.w += u.w;
            }
            As[acol+g+0][arow] = a.x; As[acol+g+1][arow] = a.y;
            As[acol+g+2][arow] = a.z; As[acol+g+3][arow] = a.w;
        }
        float4 bv = *reinterpret_cast<const float4*>(Bptr + (size_t)k0*C64);
        *reinterpret_cast<float4*>(&Bs[brow][bcol]) = bv;
        __syncthreads();
#pragma unroll
        for (int kk = 0; kk < 16; kk++) {
            float ar[8], br[4];
            *reinterpret_cast<float4*>(&ar[0]) = *reinterpret_cast<float4*>(&As[kk][ty<<3]);
            *reinterpret_cast<float4*>(&ar[4]) = *reinterpret_cast<float4*>(&As[kk][(ty<<3)+4]);
            *reinterpret_cast<float4*>(&br[0]) = *reinterpret_cast<float4*>(&Bs[kk][tx<<2]);
#pragma unroll
            for (int i = 0; i < 8; i++)
#pragma unroll
                for (int j = 0; j < 4; j++) acc[i][j] = fmaf(ar[i], br[j], acc[i][j]);
        }
        __syncthreads();
    }
#pragma unroll
    for (int j = 0; j < 4; j++) {
        int c = (tx << 2) + j;
        size_t off = ((size_t)n*C64 + c)*Pq + bm + (ty << 3);
        float4 r0 = *reinterpret_cast<const float4*>(inl + off);
        float4 r1 = *reinterpret_cast<const float4*>(inl + off + 4);
        float4 o0, o1;
        o0.x = 0.25f*acc[0][j] + r0.x; o0.y = 0.25f*acc[1][j] + r0.y;
        o0.z = 0.25f*acc[2][j] + r0.z; o0.w = 0.25f*acc[3][j] + r0.w;
        o1.x = 0.25f*acc[4][j] + r1.x; o1.y = 0.25f*acc[5][j] + r1.y;
        o1.z = 0.25f*acc[6][j] + r1.z; o1.w = 0.25f*acc[7][j] + r1.w;
        *reinterpret_cast<float4*>(out + off)     = o0;
        *reinterpret_cast<float4*>(out + off + 4) = o1;
    }
}

// ---------------- launcher ----------------
extern "C" void kernel_launch(void* const* d_in, const int* in_sizes, int n_in,
                              void* d_out, int out_size) {
    const float* input_l = (const float*)d_in[0];
    const float* input_s = (const float*)d_in[1];
    const float* w_mlb   = (const float*)d_in[2];
    const float* b_mlb   = (const float*)d_in[3];
    const float* a_mlb   = (const float*)d_in[4];
    const float* w_m     = (const float*)d_in[5];
    const float* b_m     = (const float*)d_in[6];
    const float* a_m     = (const float*)d_in[7];
    const float* w_asm   = (const float*)d_in[8];
    const float* b_asm   = (const float*)d_in[9];
    const float* a_asm   = (const float*)d_in[10];
    float* out = (float*)d_out;
    (void)in_sizes; (void)n_in; (void)out_size;

    // 1x1 convs + PReLU
    k_conv_mb  <<<dim3(Pq/256, NB), 256>>>(input_l, w_mlb, b_mlb, a_mlb);
    k_conv_ref <<<dim3(Lk/256, NB), 256>>>(input_s, w_m,   b_m,   a_m);
    k_conv_base<<<dim3(Lk/256, NB), 256>>>(input_s, w_asm, b_asm, a_asm);

    // small prep
    k_baseT  <<<(NB*Lk*C64)/256, 256>>>();
    k_S      <<<(NB*Lk)/256, 256>>>();
    k_invnorm<<<(NB*Lk)/256, 256>>>();

    // R = mb^T @ ref (K=32)  -> g_G
    k_gemm_R<<<dim3(Lk/128, Pq/128, NB), 256>>>();

    // score-side w-stencil: g_G(R) -> g_probs(T)
    k_stencil_w2<<<dim3(Lk/256, Pq, NB), 256>>>();

    // fused h-stencil + 10*invnorm scale + softmax: g_probs(T) -> g_G(probs)
    k_h_softmax<<<dim3(Pq, NB), 288>>>();

    // value-side w-stencil: g_G(probs) -> g_probs(T2)
    k_stencil_w2<<<dim3(Lk/256, Pq, NB), 256>>>();

    // y = 0.25 * hstencil(T2) @ baseT + input_l  (h-pass fused into A loads)
    k_sgemm_out<<<dim3(Pq/128, NB), 256>>>(input_l, out);
}

// round 17
// speedup vs baseline: 1.0019x; 1.0019x over previous
#include <cuda_runtime.h>
#include <cstdint>

// ---------------- problem constants ----------------
#define NB   4
#define C64  64
#define CR   32
#define HLq  96
#define WLq  96
#define HSk  48
#define WSk  48
#define Pq   (HLq*WLq)     // 9216 queries
#define Lk   (HSk*WSk)     // 2304 keys

// ---------------- device scratch (static, allocation-free) ----------------
__device__ float g_mb     [(size_t)NB*CR*Pq];    // match_base [N,32,96,96]
__device__ float g_ref    [(size_t)NB*CR*Lk];    // ref        [N,32,48,48]
__device__ float g_base   [(size_t)NB*C64*Lk];   // base       [N,64,48,48]
__device__ float g_baseT  [(size_t)NB*Lk*C64];   // base^T     [N,2304,64]
__device__ float g_S      [(size_t)NB*Lk];       // per-pixel sum of ref^2
__device__ float g_invnorm[(size_t)NB*Lk];       // 1/(||w_patch||+eps)
__device__ float g_probs  [(size_t)NB*Pq*Lk];    // ping buffer
__device__ float g_G      [(size_t)NB*Pq*Lk];    // pong buffer

// ---------------- 1x1 conv + PReLU ----------------
template<int CO, int HW>
__device__ __forceinline__ void conv_body(const float* __restrict__ in,
                                          const float* __restrict__ w,
                                          const float* __restrict__ b,
                                          const float* __restrict__ a,
                                          float* __restrict__ out) {
    __shared__ float ws[CO*64];
    __shared__ float bs[CO];
    int tid = threadIdx.x;
    for (int i = tid; i < CO*64; i += 256) ws[i] = w[i];
    for (int i = tid; i < CO;    i += 256) bs[i] = b[i];
    __syncthreads();
    float alpha = __ldg(a);
    int n = blockIdx.y;
    int p = (blockIdx.x << 8) + tid;
    const float* inp = in + (size_t)n*64*HW + p;
    float acc[CO];
#pragma unroll
    for (int co = 0; co < CO; co++) acc[co] = bs[co];
    for (int ci = 0; ci < 64; ci++) {
        float x = inp[(size_t)ci*HW];
#pragma unroll
        for (int co = 0; co < CO; co++) acc[co] = fmaf(ws[co*64+ci], x, acc[co]);
    }
    float* op = out + (size_t)n*CO*HW + p;
#pragma unroll
    for (int co = 0; co < CO; co++) {
        float v = acc[co];
        op[(size_t)co*HW] = v >= 0.f ? v : alpha*v;
    }
}

__global__ __launch_bounds__(256) void k_conv_mb(const float* __restrict__ in,
    const float* __restrict__ w, const float* __restrict__ b, const float* __restrict__ a) {
    conv_body<CR, Pq>(in, w, b, a, g_mb);
}
__global__ __launch_bounds__(256) void k_conv_ref(const float* __restrict__ in,
    const float* __restrict__ w, const float* __restrict__ b, const float* __restrict__ a) {
    conv_body<CR, Lk>(in, w, b, a, g_ref);
}
__global__ __launch_bounds__(256) void k_conv_base(const float* __restrict__ in,
    const float* __restrict__ w, const float* __restrict__ b, const float* __restrict__ a) {
    conv_body<C64, Lk>(in, w, b, a, g_base);
}

// ---------------- transpose base -> [N, L, 64] ----------------
__global__ __launch_bounds__(256) void k_baseT() {
    int idx = (blockIdx.x << 8) + threadIdx.x;     // over NB*Lk*64 (exact)
    int c = idx & 63;
    int t = idx >> 6;
    int l = t % Lk;
    int n = t / Lk;
    g_baseT[idx] = g_base[((size_t)n*C64 + c)*Lk + l];
}

// ---------------- S[n][u] = sum_c ref[n][c][u]^2 ----------------
__global__ __launch_bounds__(256) void k_S() {
    int idx = (blockIdx.x << 8) + threadIdx.x;     // over NB*Lk (exact: 36 blocks)
    int u = idx % Lk, n = idx / Lk;
    const float* r = g_ref + (size_t)n*CR*Lk + u;
    float s = 0.f;
#pragma unroll
    for (int c = 0; c < CR; c++) { float v = r[(size_t)c*Lk]; s = fmaf(v, v, s); }
    g_S[idx] = s;
}

// ---------------- invnorm[n][l] = 1/(sqrt(sum_{3x3 in-bounds} S) + eps) ----------------
__global__ __launch_bounds__(256) void k_invnorm() {
    int idx = (blockIdx.x << 8) + threadIdx.x;     // over NB*Lk
    int l = idx % Lk, n = idx / Lk;
    int hb = l / WSk, wb = l % WSk;
    const float* S = g_S + (size_t)n*Lk;
    float s = 0.f;
#pragma unroll
    for (int dy = -1; dy <= 1; dy++) {
        if ((unsigned)(hb + dy) >= HSk) continue;
#pragma unroll
        for (int dx = -1; dx <= 1; dx++) {
            if ((unsigned)(wb + dx) >= WSk) continue;
            s += S[l + dy*WSk + dx];
        }
    }
    g_invnorm[idx] = 1.f / (sqrtf(s) + 1e-4f);
}

// ---------------- R GEMM: g_G = mb^T @ ref  (M=9216, N=2304, K=32, per sample) ----------------
__global__ __launch_bounds__(256) void k_gemm_R() {
    __shared__ float As[32][128];
    __shared__ float Bs[32][128];
    const int n = blockIdx.z;
    const int bm = blockIdx.y << 7;
    const int bn = blockIdx.x << 7;
    const float* A = g_mb  + (size_t)n*CR*Pq;   // [c][p]
    const float* B = g_ref + (size_t)n*CR*Lk;   // [c][l]
    float* Cm = g_G + (size_t)n*Pq*Lk;
    const int tid = threadIdx.x;
#pragma unroll
    for (int i = 0; i < 16; i++) {
        int idx = tid + (i << 8);               // 0..4095
        int c = idx >> 7, x = idx & 127;
        As[c][x] = A[(size_t)c*Pq + bm + x];
        Bs[c][x] = B[(size_t)c*Lk + bn + x];
    }
    __syncthreads();
    const int ty = tid >> 4, tx = tid & 15;
    float acc[8][8];
#pragma unroll
    for (int i = 0; i < 8; i++)
#pragma unroll
        for (int j = 0; j < 8; j++) acc[i][j] = 0.f;
#pragma unroll
    for (int k = 0; k < 32; k++) {
        float ar[8], br[8];
        *reinterpret_cast<float4*>(&ar[0]) = *reinterpret_cast<float4*>(&As[k][ty<<3]);
        *reinterpret_cast<float4*>(&ar[4]) = *reinterpret_cast<float4*>(&As[k][(ty<<3)+4]);
        *reinterpret_cast<float4*>(&br[0]) = *reinterpret_cast<float4*>(&Bs[k][tx<<3]);
        *reinterpret_cast<float4*>(&br[4]) = *reinterpret_cast<float4*>(&Bs[k][(tx<<3)+4]);
#pragma unroll
        for (int i = 0; i < 8; i++)
#pragma unroll
            for (int j = 0; j < 8; j++) acc[i][j] = fmaf(ar[i], br[j], acc[i][j]);
    }
#pragma unroll
    for (int i = 0; i < 8; i++) {
        size_t off = (size_t)(bm + (ty<<3) + i)*Lk + bn + (tx<<3);
        *reinterpret_cast<float4*>(Cm + off)     = *reinterpret_cast<float4*>(&acc[i][0]);
        *reinterpret_cast<float4*>(Cm + off + 4) = *reinterpret_cast<float4*>(&acc[i][4]);
    }
}

// ---------------- w-pass diagonal stencil: g_G -> g_probs (used twice) ----------------
__global__ __launch_bounds__(256) void k_stencil_w2() {
    int l = (blockIdx.x << 8) + threadIdx.x;
    int p = blockIdx.y, n = blockIdx.z;
    const float* r = g_G + ((size_t)n*Pq + p) * (size_t)Lk;
    int wq = p % WLq;
    int wb = l % WSk;
    float s = r[l];
    if (wq > 0      && wb > 0)      s += r[(long)l - (Lk + 1)];
    if (wq < WLq-1  && wb < WSk-1)  s += r[(long)l + (Lk + 1)];
    g_probs[((size_t)n*Pq + p)*(size_t)Lk + l] = s;
}

// ---------------- fused h-pass stencil + scale(10*invnorm) + softmax ----------------
// reads T = g_probs rows {p-96, p, p+96}; writes probs row p to g_G
__global__ __launch_bounds__(288) void k_h_softmax() {
    int p = blockIdx.x, n = blockIdx.y;
    const float* T = g_probs + ((size_t)n*Pq + p) * (size_t)Lk;
    float* outp    = g_G     + ((size_t)n*Pq + p) * (size_t)Lk;
    const float* invn = g_invnorm + (size_t)n*Lk;
    int t = threadIdx.x;
    int hq = p / WLq;
    bool up_p = hq > 0, dn_p = hq < HLq-1;
    const float* Tu = T - (size_t)WLq*Lk - 48;   // row p-96, shifted -48
    const float* Td = T + (size_t)WLq*Lk + 48;   // row p+96, shifted +48
    float4 v[2];
    float m = -1e30f;
#pragma unroll
    for (int i = 0; i < 2; i++) {
        int f = i*288 + t;          // float4 index 0..575
        int l = f << 2;
        int hb = f / 12;            // = l/48 (float4 never straddles a 48-block)
        float4 s = *reinterpret_cast<const float4*>(T + l);
        if (up_p && hb > 0) {
            float4 u = *reinterpret_cast<const float4*>(Tu + l);
            s.x += u.x; s.y += u.y; s.z += u.z; s.w += u.w;
        }
        if (dn_p && hb < HSk-1) {
            float4 u = *reinterpret_cast<const float4*>(Td + l);
            s.x += u.x; s.y += u.y; s.z += u.z; s.w += u.w;
        }
        float4 iv = *reinterpret_cast<const float4*>(invn + l);
        s.x *= 10.f*iv.x; s.y *= 10.f*iv.y; s.z *= 10.f*iv.z; s.w *= 10.f*iv.w;
        v[i] = s;
        m = fmaxf(m, fmaxf(fmaxf(s.x, s.y), fmaxf(s.z, s.w)));
    }
    __shared__ float red[9];
    __shared__ float bval;
#pragma unroll
    for (int o = 16; o > 0; o >>= 1) m = fmaxf(m, __shfl_xor_sync(0xffffffffu, m, o));
    if ((t & 31) == 0) red[t >> 5] = m;
    __syncthreads();
    if (t == 0) {
        float x = red[0];
#pragma unroll
        for (int i = 1; i < 9; i++) x = fmaxf(x, red[i]);
        bval = x;
    }
    __syncthreads();
    float mm = bval;
    float s = 0.f;
#pragma unroll
    for (int i = 0; i < 2; i++) {
        v[i].x = expf(v[i].x - mm); v[i].y = expf(v[i].y - mm);
        v[i].z = expf(v[i].z - mm); v[i].w = expf(v[i].w - mm);
        s += v[i].x + v[i].y + v[i].z + v[i].w;
    }
#pragma unroll
    for (int o = 16; o > 0; o >>= 1) s += __shfl_xor_sync(0xffffffffu, s, o);
    if ((t & 31) == 0) red[t >> 5] = s;
    __syncthreads();
    if (t == 0) {
        float x = 0.f;
#pragma unroll
        for (int i = 0; i < 9; i++) x += red[i];
        bval = x;
    }
    __syncthreads();
    float inv = 1.f / bval;
#pragma unroll
    for (int i = 0; i < 2; i++) {
        int l = (i*288 + t) << 2;
        float4 o;
        o.x = v[i].x*inv; o.y = v[i].y*inv; o.z = v[i].z*inv; o.w = v[i].w*inv;
        *reinterpret_cast<float4*>(outp + l) = o;
    }
}

// ---------------- output GEMM with fused h-pass on A: ----------------
// A[p,k] = T2[p,k] + m*T2[p-96,k-48] + m*T2[p+96,k+48]  (T2 = g_probs)
// y = 0.25 * A @ baseT + input_l ; M=9216, N=64, K=2304; 128x64 tile, BK=16
__global__ __launch_bounds__(256) void k_sgemm_out(const float* __restrict__ inl,
                                                   float* __restrict__ out) {
    __shared__ float As[16][128];
    __shared__ float Bs[16][64];
    const int n = blockIdx.y;
    const float* A = g_probs + (size_t)n*Pq*Lk;
    const float* B = g_baseT + (size_t)n*Lk*C64;
    const int bm = blockIdx.x << 7;
    const int tid  = threadIdx.x;
    const int arow = tid & 127, acol = (tid >> 7) << 3;   // 0 or 8
    const int brow = tid >> 4,  bcol = (tid & 15) << 2;
    const int ty = tid >> 4, tx = tid & 15;
    const int p = bm + arow;
    const int hq = p / WLq;
    const bool up_p = hq > 0, dn_p = hq < HLq-1;
    const float* Ap  = A + (size_t)p*Lk;
    const float* Apu = Ap - (size_t)WLq*Lk - 48;
    const float* Apd = Ap + (size_t)WLq*Lk + 48;
    const float* Bptr = B + (size_t)brow*C64 + bcol;
    float acc[8][4];
#pragma unroll
    for (int i = 0; i < 8; i++)
#pragma unroll
        for (int j = 0; j < 4; j++) acc[i][j] = 0.f;
    for (int k0 = 0; k0 < Lk; k0 += 16) {
#pragma unroll
        for (int g = 0; g < 8; g += 4) {
            int k = k0 + acol + g;
            int hb = k / 48;                    // float4 never straddles (48%4==0)
            float4 a = *reinterpret_cast<const float4*>(Ap + k);
            if (up_p && hb > 0) {
                float4 u = *reinterpret_cast<const float4*>(Apu + k);
                a.x += u.x; a.y += u.y; a.z += u.z; a.w += u.w;
            }
            if (dn_p && hb < HSk-1) {
                float4 u = *reinterpret_cast<const float4*>(Apd + k);
                a.x += u.x; a.y += u.y; a.z += u.z; a.w += u.w;
            }
            As[acol+g+0][arow] = a.x; As[acol+g+1][arow] = a.y;
            As[acol+g+2][arow] = a.z; As[acol+g+3][arow] = a.w;
        }
        float4 bv = *reinterpret_cast<const float4*>(Bptr + (size_t)k0*C64);
        *reinterpret_cast<float4*>(&Bs[brow][bcol]) = bv;
        __syncthreads();
#pragma unroll
        for (int kk = 0; kk < 16; kk++) {
            float ar[8], br[4];
            *reinterpret_cast<float4*>(&ar[0]) = *reinterpret_cast<float4*>(&As[kk][ty<<3]);
            *reinterpret_cast<float4*>(&ar[4]) = *reinterpret_cast<float4*>(&As[kk][(ty<<3)+4]);
            *reinterpret_cast<float4*>(&br[0]) = *reinterpret_cast<float4*>(&Bs[kk][tx<<2]);
#pragma unroll
            for (int i = 0; i < 8; i++)
#pragma unroll
                for (int j = 0; j < 4; j++) acc[i][j] = fmaf(ar[i], br[j], acc[i][j]);
        }
        __syncthreads();
    }
#pragma unroll
    for (int j = 0; j < 4; j++) {
        int c = (tx << 2) + j;
        size_t off = ((size_t)n*C64 + c)*Pq + bm + (ty << 3);
        float4 r0 = *reinterpret_cast<const float4*>(inl + off);
        float4 r1 = *reinterpret_cast<const float4*>(inl + off + 4);
        float4 o0, o1;
        o0.x = 0.25f*acc[0][j] + r0.x; o0.y = 0.25f*acc[1][j] + r0.y;
        o0.z = 0.25f*acc[2][j] + r0.z; o0.w = 0.25f*acc[3][j] + r0.w;
        o1.x = 0.25f*acc[4][j] + r1.x; o1.y = 0.25f*acc[5][j] + r1.y;
        o1.z = 0.25f*acc[6][j] + r1.z; o1.w = 0.25f*acc[7][j] + r1.w;
        *reinterpret_cast<float4*>(out + off)     = o0;
        *reinterpret_cast<float4*>(out + off + 4) = o1;
    }
}

// ---------------- launcher ----------------
extern "C" void kernel_launch(void* const* d_in, const int* in_sizes, int n_in,
                              void* d_out, int out_size) {
    const float* input_l = (const float*)d_in[0];
    const float* input_s = (const float*)d_in[1];
    const float* w_mlb   = (const float*)d_in[2];
    const float* b_mlb   = (const float*)d_in[3];
    const float* a_mlb   = (const float*)d_in[4];
    const float* w_m     = (const float*)d_in[5];
    const float* b_m     = (const float*)d_in[6];
    const float* a_m     = (const float*)d_in[7];
    const float* w_asm   = (const float*)d_in[8];
    const float* b_asm   = (const float*)d_in[9];
    const float* a_asm   = (const float*)d_in[10];
    float* out = (float*)d_out;
    (void)in_sizes; (void)n_in; (void)out_size;

    // 1x1 convs + PReLU
    k_conv_mb  <<<dim3(Pq/256, NB), 256>>>(input_l, w_mlb, b_mlb, a_mlb);
    k_conv_ref <<<dim3(Lk/256, NB), 256>>>(input_s, w_m,   b_m,   a_m);
    k_conv_base<<<dim3(Lk/256, NB), 256>>>(input_s, w_asm, b_asm, a_asm);

    // small prep
    k_baseT  <<<(NB*Lk*C64)/256, 256>>>();
    k_S      <<<(NB*Lk)/256, 256>>>();
    k_invnorm<<<(NB*Lk)/256, 256>>>();

    // R = mb^T @ ref (K=32)  -> g_G
    k_gemm_R<<<dim3(Lk/128, Pq/128, NB), 256>>>();

    // score-side w-stencil: g_G(R) -> g_probs(T)
    k_stencil_w2<<<dim3(Lk/256, Pq, NB), 256>>>();

    // fused h-stencil + 10*invnorm scale + softmax: g_probs(T) -> g_G(probs)
    k_h_softmax<<<dim3(Pq, NB), 288>>>();

    // value-side w-stencil: g_G(probs) -> g_probs(T2)
    k_stencil_w2<<<dim3(Lk/256, Pq, NB), 256>>>();

    // y = 0.25 * hstencil(T2) @ baseT + input_l  (h-pass fused into A loads)
    k_sgemm_out<<<dim3(Pq/128, NB), 256>>>(input_l, out);
}